// round 13
// baseline (speedup 1.0000x reference)
#include <cuda_runtime.h>
#include <cuda_bf16.h>
#include <cstdint>

// ---------------- problem constants ----------------
#define BATCH    4096
#define NDIMS    19
#define D        256
#define NROWS    8192
#define NBLK     64                    // 64 row-blocks of 128
#define NCTA     148
#define INV_T    14.285714285714286f
#define C2EXP    (14.285714285714286f * 1.4426950408889634f)   // INV_T * log2(e)
#define CAPR     32                    // positive slots per row
#define NTHREADS 512
#define TILEB    32768                 // 128 rows x 256 bytes (fp8)
#define GWARPS   (NCTA * 16)           // 2368 global warps
#define RANKN    (BATCH * NDIMS)       // 77824

// ---------------- device scratch ----------------
__device__ uint32_t g_Z8[NROWS * 64];         // normalized e4m3 rows (4 per u32)
__device__ int      g_pieces[NROWS];
__device__ float    g_negS[NROWS];            // atomically accumulated neg sums
__device__ float    g_posv[NROWS * CAPR];
__device__ int      g_pcnt[NROWS];
__device__ float    g_rankS[NCTA];
__device__ int      g_rankC[NCTA];
__device__ float    g_totS[NCTA];
__device__ int      g_totC[NCTA];
__device__ unsigned long long g_barCount;     // monotonic, never reset

// ---------------- helpers ----------------
__device__ __forceinline__ uint32_t smem_u32(const void* p) {
    return (uint32_t)__cvta_generic_to_shared(p);
}
__device__ __forceinline__ float ex2(float x) {
    float r;
    asm("ex2.approx.f32 %0, %1;" : "=f"(r) : "f"(x));
    return r;
}
__device__ __forceinline__ uint32_t fp8x4(float f0, float f1, float f2, float f3) {
    uint16_t lo, hi;
    asm("cvt.rn.satfinite.e4m3x2.f32 %0, %1, %2;" : "=h"(lo) : "f"(f1), "f"(f0));
    asm("cvt.rn.satfinite.e4m3x2.f32 %0, %1, %2;" : "=h"(hi) : "f"(f3), "f"(f2));
    return (uint32_t)lo | ((uint32_t)hi << 16);
}
__device__ __forceinline__ void mmaf8(float d[4], const uint32_t a[4],
                                      const uint32_t b[2]) {
    asm volatile(
        "mma.sync.aligned.m16n8k32.row.col.f32.e4m3.e4m3.f32 "
        "{%0,%1,%2,%3}, {%4,%5,%6,%7}, {%8,%9}, {%0,%1,%2,%3};\n"
        : "+f"(d[0]), "+f"(d[1]), "+f"(d[2]), "+f"(d[3])
        : "r"(a[0]), "r"(a[1]), "r"(a[2]), "r"(a[3]), "r"(b[0]), "r"(b[1]));
}
__device__ __forceinline__ void ldsm4(uint32_t addr, uint32_t r[4]) {
    asm volatile("ldmatrix.sync.aligned.m8n8.x4.shared.b16 {%0,%1,%2,%3}, [%4];"
                 : "=r"(r[0]), "=r"(r[1]), "=r"(r[2]), "=r"(r[3]) : "r"(addr));
}
__device__ __forceinline__ void cp16(uint32_t dst, const void* src) {
    uint64_t gs;
    asm("cvta.to.global.u64 %0, %1;" : "=l"(gs) : "l"(src));
    asm volatile("cp.async.cg.shared.global [%0], [%1], 16;" :: "r"(dst), "l"(gs));
}
#define CP_COMMIT() asm volatile("cp.async.commit_group;" ::: "memory")
#define CP_WAIT0()  asm volatile("cp.async.wait_group 0;" ::: "memory")
#define CP_WAIT1()  asm volatile("cp.async.wait_group 1;" ::: "memory")

// grid barrier: monotonic counter, multiple-of-NCTA invariant preserved per launch
__device__ __forceinline__ void grid_barrier(bool wait) {
    __shared__ unsigned long long s_target;
    __syncthreads();
    if (threadIdx.x == 0) {
        __threadfence();
        unsigned long long t = atomicAdd(&g_barCount, 1ULL);
        if (wait) {
            unsigned long long target = t - (t % NCTA) + NCTA;
            s_target = target;
            volatile unsigned long long* p = &g_barCount;
            while (*p < target) __nanosleep(64);
        }
    }
    if (wait) { __syncthreads(); __threadfence(); }
}

// 128x256B fp8 tile -> 256B rows with XOR-16B-chunk swizzle: chunk' = ch ^ (row&7)
__device__ __forceinline__ void cp_tile(uint32_t dstBase, int row0) {
    const char* src = (const char*)g_Z8 + (size_t)row0 * 256;
    #pragma unroll
    for (int it = 0; it < 4; it++) {
        int idx = it * NTHREADS + threadIdx.x;
        int r = idx >> 4, ch = idx & 15;
        cp16(dstBase + r * 256 + ((ch ^ (r & 7)) << 4), src + r * 256 + ch * 16);
    }
}

// ---------------- THE fused persistent kernel ----------------
__global__ void __launch_bounds__(NTHREADS, 1) fused_kernel(
    const float* __restrict__ za, const float* __restrict__ zb,
    const float* __restrict__ logits,
    const float* __restrict__ la, const float* __restrict__ lb,
    const int* __restrict__ pa, const int* __restrict__ pb,
    float* __restrict__ out, int out_size) {

    extern __shared__ uint8_t dsm[];
    __shared__ int   s_pi[128];
    __shared__ int   s_pj[128];
    __shared__ float s_rowRed[128][8];
    __shared__ float s_colRed[128][2];
    __shared__ float s_wS[16];
    __shared__ int   s_wC[16];

    const int tid  = threadIdx.x;
    const int warp = tid >> 5;
    const int lane = tid & 31;
    const int cta  = blockIdx.x;
    const int gw   = cta * 16 + warp;

    // ================= phase 0: normalize -> fp8, zero accum, ranking =======
    for (int row = gw; row < NROWS; row += GWARPS) {
        const float* src = (row < BATCH) ? (za + (size_t)row * D)
                                         : (zb + (size_t)(row - BATCH) * D);
        int k0 = lane * 4;
        float4 v0 = *(const float4*)(src + k0);
        float4 v1 = *(const float4*)(src + k0 + 128);
        float ss = v0.x*v0.x + v0.y*v0.y + v0.z*v0.z + v0.w*v0.w
                 + v1.x*v1.x + v1.y*v1.y + v1.z*v1.z + v1.w*v1.w;
        #pragma unroll
        for (int off = 16; off; off >>= 1) ss += __shfl_xor_sync(0xffffffffu, ss, off);
        float inv = 1.0f / fmaxf(sqrtf(ss), 1e-8f);
        uint32_t* dst = g_Z8 + (size_t)row * 64;
        dst[lane]      = fp8x4(v0.x * inv, v0.y * inv, v0.z * inv, v0.w * inv);
        dst[32 + lane] = fp8x4(v1.x * inv, v1.y * inv, v1.z * inv, v1.w * inv);
        if (lane == 0) {
            g_pieces[row] = (row < BATCH) ? pa[row] : pb[row - BATCH];
            g_pcnt[row]   = 0;
            g_negS[row]   = 0.f;
        }
    }
    // ranking partials -> per-CTA slot
    {
        float sum = 0.f; int cnt = 0;
        for (int i = cta * NTHREADS + tid; i < RANKN; i += NCTA * NTHREADS) {
            float diff = la[i] - lb[i];
            if (fabsf(diff) >= 0.05f) {
                float t = (diff > 0.f ? 0.9f : 0.f) + 0.05f;
                float l = logits[i];
                sum += fmaxf(l, 0.f) - l * t + log1pf(__expf(-fabsf(l)));
                cnt++;
            }
        }
        #pragma unroll
        for (int o = 16; o; o >>= 1) {
            sum += __shfl_xor_sync(0xffffffffu, sum, o);
            cnt += __shfl_xor_sync(0xffffffffu, cnt, o);
        }
        if (lane == 0) { s_wS[warp] = sum; s_wC[warp] = cnt; }
        __syncthreads();
        if (tid == 0) {
            float s = 0.f; int c2 = 0;
            #pragma unroll
            for (int k = 0; k < 16; k++) { s += s_wS[k]; c2 += s_wC[k]; }
            g_rankS[cta] = s; g_rankC[cta] = c2;
        }
    }
    grid_barrier(true);

    // ================= phase 1: symmetric FP8 GEMM + fused masked LSE =======
    {
        const int wm = warp >> 3, wn = warp & 7, q = lane >> 2;
        const uint32_t sbase = smem_u32(dsm);
        const uint32_t bufA  = sbase;
        const uint32_t bufB0 = sbase + TILEB;
        const uint32_t bufB1 = sbase + 2 * TILEB;

        const int ustart = cta * 14 + (cta < 8 ? cta : 8);
        const int ucount = 14 + (cta < 8 ? 1 : 0);
        int ib = 0, rem = ustart;
        while (rem >= NBLK - ib) { rem -= NBLK - ib; ib++; }
        int jb = ib + rem;

        cp_tile(bufA, ib * 128);
        cp_tile(bufB0, jb * 128);
        CP_COMMIT();
        if (tid < 128) s_pi[tid] = g_pieces[ib * 128 + tid];

        const uint32_t aRow = bufA + (uint32_t)(wm * 64 + (lane & 15)) * 256;
        const uint32_t bRowOff =
            (uint32_t)(wn * 16 + ((lane >> 4) & 1) * 8 + (lane & 7)) * 256;
        const uint32_t ax = (uint32_t)(lane >> 4);
        const uint32_t bx = (uint32_t)((lane >> 3) & 1);
        const uint32_t xr = (uint32_t)(lane & 7);

        for (int un = 0; un < ucount; un++) {
            const int par = un & 1;
            int nib = ib, njb = jb + 1;
            if (njb == NBLK) { nib = ib + 1; njb = nib; }
            const bool hasNext = (un + 1 < ucount);

            if (hasNext) {
                cp_tile(par ? bufB0 : bufB1, njb * 128);
                CP_COMMIT();
                CP_WAIT1();
            } else {
                CP_WAIT0();
            }
            __syncthreads();

            if (tid < 128) s_pj[tid] = g_pieces[jb * 128 + tid];

            int mypc[8];
            #pragma unroll
            for (int mt = 0; mt < 4; mt++)
                #pragma unroll
                for (int h = 0; h < 2; h++)
                    mypc[mt * 2 + h] = s_pi[wm * 64 + mt * 16 + q + 8 * h];

            float acc[4][2][4];
            #pragma unroll
            for (int mt = 0; mt < 4; mt++)
                #pragma unroll
                for (int nt = 0; nt < 2; nt++)
                    #pragma unroll
                    for (int e = 0; e < 4; e++) acc[mt][nt][e] = 0.f;

            const uint32_t bRow = (par ? bufB1 : bufB0) + bRowOff;

            uint32_t afr[2][4][4], bfr[2][2][2];
            {
                const uint32_t aoff = ((ax ^ xr) << 4);
                const uint32_t boff = ((bx ^ xr) << 4);
                #pragma unroll
                for (int mt = 0; mt < 4; mt++)
                    ldsm4(aRow + (uint32_t)mt * 4096 + aoff, afr[0][mt]);
                uint32_t r[4];
                ldsm4(bRow + boff, r);
                bfr[0][0][0] = r[0]; bfr[0][0][1] = r[1];
                bfr[0][1][0] = r[2]; bfr[0][1][1] = r[3];
            }
            #pragma unroll
            for (int ks = 0; ks < 8; ks++) {
                const int cur = ks & 1, nxt = cur ^ 1;
                if (ks < 7) {
                    const uint32_t aoff = (((ax + (uint32_t)(ks + 1) * 2) ^ xr) << 4);
                    const uint32_t boff = (((bx + (uint32_t)(ks + 1) * 2) ^ xr) << 4);
                    #pragma unroll
                    for (int mt = 0; mt < 4; mt++)
                        ldsm4(aRow + (uint32_t)mt * 4096 + aoff, afr[nxt][mt]);
                    uint32_t r[4];
                    ldsm4(bRow + boff, r);
                    bfr[nxt][0][0] = r[0]; bfr[nxt][0][1] = r[1];
                    bfr[nxt][1][0] = r[2]; bfr[nxt][1][1] = r[3];
                }
                #pragma unroll
                for (int mt = 0; mt < 4; mt++)
                    #pragma unroll
                    for (int nt = 0; nt < 2; nt++)
                        mmaf8(acc[mt][nt], afr[cur][mt], bfr[cur][nt]);
            }
            __syncthreads();

            const bool isDiag = (ib == jb);
            int pjc[4];
            #pragma unroll
            for (int nt = 0; nt < 2; nt++)
                #pragma unroll
                for (int cc = 0; cc < 2; cc++)
                    pjc[nt * 2 + cc] = s_pj[wn * 16 + nt * 8 + (lane & 3) * 2 + cc];

            const int jgBase = jb * 128 + wn * 16 + (lane & 3) * 2;
            float colacc[4] = {0.f, 0.f, 0.f, 0.f};

            #pragma unroll
            for (int mt = 0; mt < 4; mt++)
                #pragma unroll
                for (int h = 0; h < 2; h++) {
                    const int rloc = wm * 64 + mt * 16 + q + 8 * h;
                    const int ig = ib * 128 + rloc;
                    const int myp = mypc[mt * 2 + h];
                    float na = 0.f;
                    #pragma unroll
                    for (int nt = 0; nt < 2; nt++)
                        #pragma unroll
                        for (int cc = 0; cc < 2; cc++) {
                            float dot = acc[mt][nt][h * 2 + cc];
                            float e = ex2(fmaf(dot, C2EXP, -C2EXP));
                            bool same = (pjc[nt * 2 + cc] == myp);
                            na += same ? 0.f : e;
                            colacc[nt * 2 + cc] += same ? 0.f : e;
                            if (same) {
                                int jg = jgBase + nt * 8 + cc;
                                if (!isDiag || jg != ig) {
                                    float sim = dot * INV_T;
                                    int sl = atomicAdd(&g_pcnt[ig], 1);
                                    if (sl < CAPR) g_posv[ig * CAPR + sl] = sim;
                                    if (!isDiag) {
                                        int sl2 = atomicAdd(&g_pcnt[jg], 1);
                                        if (sl2 < CAPR) g_posv[jg * CAPR + sl2] = sim;
                                    }
                                }
                            }
                        }
                    na += __shfl_xor_sync(0xffffffffu, na, 1);
                    na += __shfl_xor_sync(0xffffffffu, na, 2);
                    if ((lane & 3) == 0) s_rowRed[rloc][wn] = na;
                }

            if (!isDiag) {
                #pragma unroll
                for (int idx = 0; idx < 4; idx++) {
                    colacc[idx] += __shfl_xor_sync(0xffffffffu, colacc[idx], 4);
                    colacc[idx] += __shfl_xor_sync(0xffffffffu, colacc[idx], 8);
                    colacc[idx] += __shfl_xor_sync(0xffffffffu, colacc[idx], 16);
                }
                if (lane < 4) {
                    #pragma unroll
                    for (int nt = 0; nt < 2; nt++)
                        #pragma unroll
                        for (int cc = 0; cc < 2; cc++)
                            s_colRed[wn * 16 + nt * 8 + lane * 2 + cc][wm] =
                                colacc[nt * 2 + cc];
                }
            }
            __syncthreads();

            if (tid < 128) {
                float v = 0.f;
                #pragma unroll
                for (int k = 0; k < 8; k++) v += s_rowRed[tid][k];
                atomicAdd(&g_negS[ib * 128 + tid], v);
                if (!isDiag) {
                    float w = s_colRed[tid][0] + s_colRed[tid][1];
                    atomicAdd(&g_negS[jb * 128 + tid], w);
                }
            }

            if (hasNext && nib != ib) {
                cp_tile(bufA, nib * 128);
                CP_COMMIT();
                if (tid < 128) s_pi[tid] = g_pieces[nib * 128 + tid];
            }
            ib = nib; jb = njb;
        }
    }
    grid_barrier(true);

    // ================= phase 2: per-row merge -> per-CTA totals =============
    {
        float accS = 0.f; int accC = 0;
        for (int row = gw; row < NROWS; row += GWARPS) {
            float S = g_negS[row];
            int n = g_pcnt[row];
            if (n > CAPR) n = CAPR;
            float sum = 0.f;
            if (S > 0.f) {
                float nl = INV_T + logf(S);
                if (lane < n) {
                    float d = nl - g_posv[row * CAPR + lane];
                    sum = (d > 0.f) ? (d + log1pf(__expf(-d))) : log1pf(__expf(d));
                }
            } else {
                n = 0;
            }
            #pragma unroll
            for (int o = 16; o; o >>= 1) sum += __shfl_xor_sync(0xffffffffu, sum, o);
            accS += sum; accC += n;
        }
        if (lane == 0) { s_wS[warp] = accS; s_wC[warp] = accC; }
        __syncthreads();
        if (tid == 0) {
            float s = 0.f; int c2 = 0;
            #pragma unroll
            for (int k = 0; k < 16; k++) { s += s_wS[k]; c2 += s_wC[k]; }
            g_totS[cta] = s; g_totC[cta] = c2;
        }
    }
    grid_barrier(cta == 0);

    // ================= phase 3: CTA 0 final reduce + write ==================
    if (cta == 0 && warp == 0) {
        float ts = 0.f, rs = 0.f; int tc = 0, rc = 0;
        for (int k = lane; k < NCTA; k += 32) {
            ts += g_totS[k]; tc += g_totC[k];
            rs += g_rankS[k]; rc += g_rankC[k];
        }
        #pragma unroll
        for (int o = 16; o; o >>= 1) {
            ts += __shfl_xor_sync(0xffffffffu, ts, o);
            tc += __shfl_xor_sync(0xffffffffu, tc, o);
            rs += __shfl_xor_sync(0xffffffffu, rs, o);
            rc += __shfl_xor_sync(0xffffffffu, rc, o);
        }
        if (lane == 0) {
            float lcon  = (tc > 0) ? (ts / (float)tc) : 0.f;
            float lrank = (rc > 0) ? (rs / (float)rc) : 0.f;
            out[0] = lrank + 0.3f * lcon;
            if (out_size > 1) out[1] = lrank;
            if (out_size > 2) out[2] = lcon;
        }
    }
}

// ---------------- launch ----------------
extern "C" void kernel_launch(void* const* d_in, const int* in_sizes, int n_in,
                              void* d_out, int out_size) {
    const float* za     = (const float*)d_in[0];
    const float* zb     = (const float*)d_in[1];
    const float* logits = (const float*)d_in[2];
    const float* la     = (const float*)d_in[3];
    const float* lb     = (const float*)d_in[4];
    const int*   pa     = (const int*)d_in[5];
    const int*   pb     = (const int*)d_in[6];
    float* out = (float*)d_out;

    const int dynSmem = 3 * TILEB;   // 98304 bytes
    cudaFuncSetAttribute(fused_kernel,
                         cudaFuncAttributeMaxDynamicSharedMemorySize, dynSmem);

    fused_kernel<<<NCTA, NTHREADS, dynSmem>>>(za, zb, logits, la, lb, pa, pb,
                                              out, out_size);
}